// round 8
// baseline (speedup 1.0000x reference)
#include <cuda_runtime.h>

#define HH 50
#define TT 96
#define NPRED 12
#define NTH 64
#define EPB 2   // batch elements per block (per thread) — weights shared in registers

typedef unsigned long long u64;

__device__ __forceinline__ u64 pk2(float lo, float hi) {
    u64 r; asm("mov.b64 %0, {%1,%2};" : "=l"(r) : "f"(lo), "f"(hi)); return r;
}
__device__ __forceinline__ void upk2(u64 v, float &lo, float &hi) {
    asm("mov.b64 {%0,%1}, %2;" : "=f"(lo), "=f"(hi) : "l"(v));
}
__device__ __forceinline__ u64 ffma2(u64 a, u64 b, u64 c) {
    u64 d; asm("fma.rn.f32x2 %0, %1, %2, %3;" : "=l"(d) : "l"(a), "l"(b), "l"(c)); return d;
}
__device__ __forceinline__ u64 add2(u64 a, u64 b) {
    u64 d; asm("add.rn.f32x2 %0, %1, %2;" : "=l"(d) : "l"(a), "l"(b)); return d;
}
__device__ __forceinline__ float ftanh(float x) {
    float y; asm("tanh.approx.f32 %0, %1;" : "=f"(y) : "f"(x)); return y;
}

__global__ __launch_bounds__(NTH)
void lstm_recursive_kernel(const float* __restrict__ x,
                           const float* __restrict__ W_ih,
                           const float* __restrict__ W_hh,
                           const float* __restrict__ b_ih,
                           const float* __restrict__ b_hh,
                           const float* __restrict__ W_fc,
                           const float* __restrict__ b_fc,
                           float* __restrict__ out) {
    const int j  = threadIdx.x;
    const int b0 = blockIdx.x * EPB;

    // h stored DUPLICATED: sh[e][buf][k] = (h_k, h_k) as u64 — one LDS.128 feeds 2 k's
    __shared__ __align__(16) u64 sh[EPB][2][52];
    __shared__ float swin[EPB][TT + NPRED];
    __shared__ float sred[EPB][HH];

#pragma unroll
    for (int e = 0; e < EPB; e++)
        for (int i = j; i < TT; i += NTH) swin[e][i] = x[(b0 + e) * TT + i];

    // Gate-pair packed weights, sigmoid 0.5-prescale folded into i,f,o rows.
    // wIF[k] = (0.5*Wi[j][k], 0.5*Wf[j][k]);  wGO[k] = (Wg[j][k], 0.5*Wo[j][k])
    u64 wIF[HH], wGO[HH];
    u64 xwIF = 0, xwGO = 0, bIF = 0, bGO = 0;
    float wfc = 0.0f;
    if (j < HH) {
        const float* Wi = W_hh + (0 * HH + j) * HH;
        const float* Wf = W_hh + (1 * HH + j) * HH;
        const float* Wg = W_hh + (2 * HH + j) * HH;
        const float* Wo = W_hh + (3 * HH + j) * HH;
#pragma unroll
        for (int k = 0; k < HH; k++) {
            wIF[k] = pk2(0.5f * Wi[k], 0.5f * Wf[k]);
            wGO[k] = pk2(Wg[k], 0.5f * Wo[k]);
        }
        xwIF = pk2(0.5f * W_ih[j], 0.5f * W_ih[HH + j]);
        xwGO = pk2(W_ih[2 * HH + j], 0.5f * W_ih[3 * HH + j]);
        bIF  = pk2(0.5f * (b_ih[j] + b_hh[j]),
                   0.5f * (b_ih[HH + j] + b_hh[HH + j]));
        bGO  = pk2(b_ih[2 * HH + j] + b_hh[2 * HH + j],
                   0.5f * (b_ih[3 * HH + j] + b_hh[3 * HH + j]));
        wfc = W_fc[j];
    }
    const float bfc = b_fc[0];

    for (int p = 0; p < NPRED; p++) {
        if (j < 52) {
#pragma unroll
            for (int e = 0; e < EPB; e++) { sh[e][0][j] = 0ull; sh[e][1][j] = 0ull; }
        }
        float c[EPB], hnew[EPB];
#pragma unroll
        for (int e = 0; e < EPB; e++) { c[e] = 0.0f; hnew[e] = 0.0f; }
        __syncthreads();

#pragma unroll 1
        for (int t = 0; t < TT; t++) {
            const int buf = t & 1;
            if (j < HH) {
                // 2 chains per gate-pair per element -> 8 independent FFMA2 chains
                u64 aIF0[EPB], aIF1[EPB], aGO0[EPB], aGO1[EPB];
#pragma unroll
                for (int e = 0; e < EPB; e++) {
                    const float xt = swin[e][p + t];
                    const u64 xd = pk2(xt, xt);
                    aIF0[e] = ffma2(xd, xwIF, bIF);
                    aGO0[e] = ffma2(xd, xwGO, bGO);
                    aIF1[e] = 0ull;
                    aGO1[e] = 0ull;
                }
                const ulonglong2* h0 = (const ulonglong2*)sh[0][buf];
                const ulonglong2* h1 = (const ulonglong2*)sh[1][buf];
#pragma unroll
                for (int kk = 0; kk < 12; kk++) {     // k = 4kk .. 4kk+3
                    ulonglong2 dA0 = h0[2 * kk],     dB0 = h1[2 * kk];      // (h,h)(h,h)
                    ulonglong2 dA1 = h0[2 * kk + 1], dB1 = h1[2 * kk + 1];
                    aIF0[0] = ffma2(wIF[4 * kk], dA0.x, aIF0[0]);
                    aGO0[0] = ffma2(wGO[4 * kk], dA0.x, aGO0[0]);
                    aIF0[1] = ffma2(wIF[4 * kk], dB0.x, aIF0[1]);
                    aGO0[1] = ffma2(wGO[4 * kk], dB0.x, aGO0[1]);
                    aIF1[0] = ffma2(wIF[4 * kk + 1], dA0.y, aIF1[0]);
                    aGO1[0] = ffma2(wGO[4 * kk + 1], dA0.y, aGO1[0]);
                    aIF1[1] = ffma2(wIF[4 * kk + 1], dB0.y, aIF1[1]);
                    aGO1[1] = ffma2(wGO[4 * kk + 1], dB0.y, aGO1[1]);
                    aIF0[0] = ffma2(wIF[4 * kk + 2], dA1.x, aIF0[0]);
                    aGO0[0] = ffma2(wGO[4 * kk + 2], dA1.x, aGO0[0]);
                    aIF0[1] = ffma2(wIF[4 * kk + 2], dB1.x, aIF0[1]);
                    aGO0[1] = ffma2(wGO[4 * kk + 2], dB1.x, aGO0[1]);
                    aIF1[0] = ffma2(wIF[4 * kk + 3], dA1.y, aIF1[0]);
                    aGO1[0] = ffma2(wGO[4 * kk + 3], dA1.y, aGO1[0]);
                    aIF1[1] = ffma2(wIF[4 * kk + 3], dB1.y, aIF1[1]);
                    aGO1[1] = ffma2(wGO[4 * kk + 3], dB1.y, aGO1[1]);
                }
                {   // k = 48, 49
                    ulonglong2 dA = h0[24], dB = h1[24];
                    aIF0[0] = ffma2(wIF[48], dA.x, aIF0[0]);
                    aGO0[0] = ffma2(wGO[48], dA.x, aGO0[0]);
                    aIF0[1] = ffma2(wIF[48], dB.x, aIF0[1]);
                    aGO0[1] = ffma2(wGO[48], dB.x, aGO0[1]);
                    aIF1[0] = ffma2(wIF[49], dA.y, aIF1[0]);
                    aGO1[0] = ffma2(wGO[49], dA.y, aGO1[0]);
                    aIF1[1] = ffma2(wIF[49], dB.y, aIF1[1]);
                    aGO1[1] = ffma2(wGO[49], dB.y, aGO1[1]);
                }
#pragma unroll
                for (int e = 0; e < EPB; e++) {
                    u64 gIF = add2(aIF0[e], aIF1[e]);
                    u64 gGO = add2(aGO0[e], aGO1[e]);
                    float zi, zf, zg, zo;
                    upk2(gIF, zi, zf);                 // already 0.5-prescaled
                    upk2(gGO, zg, zo);                 // zo 0.5-prescaled, zg raw
                    const float i_ = fmaf(0.5f, ftanh(zi), 0.5f);
                    const float f_ = fmaf(0.5f, ftanh(zf), 0.5f);
                    const float g_ = ftanh(zg);
                    const float o_ = fmaf(0.5f, ftanh(zo), 0.5f);
                    c[e]    = fmaf(f_, c[e], i_ * g_);
                    hnew[e] = o_ * ftanh(c[e]);
                    sh[e][buf ^ 1][j] = pk2(hnew[e], hnew[e]);   // duplicated store
                }
            }
            __syncthreads();
        }

        // FC head: out = h . W_fc + b_fc, then slide window
        if (j < HH) {
#pragma unroll
            for (int e = 0; e < EPB; e++) sred[e][j] = hnew[e] * wfc;
        }
        __syncthreads();
        if (j < EPB) {
            float s = bfc;
#pragma unroll
            for (int k = 0; k < HH; k++) s += sred[j][k];
            swin[j][TT + p] = s;
            out[(b0 + j) * NPRED + p] = s;
        }
        __syncthreads();
    }
}

extern "C" void kernel_launch(void* const* d_in, const int* in_sizes, int n_in,
                              void* d_out, int out_size) {
    const float* x    = (const float*)d_in[0];
    const float* W_ih = (const float*)d_in[1];
    const float* W_hh = (const float*)d_in[2];
    const float* b_ih = (const float*)d_in[3];
    const float* b_hh = (const float*)d_in[4];
    const float* W_fc = (const float*)d_in[5];
    const float* b_fc = (const float*)d_in[6];
    float* out = (float*)d_out;

    const int B = out_size / NPRED;               // 1024
    lstm_recursive_kernel<<<B / EPB, NTH>>>(x, W_ih, W_hh, b_ih, b_hh, W_fc, b_fc, out);
}

// round 10
// speedup vs baseline: 1.0617x; 1.0617x over previous
#include <cuda_runtime.h>

#define HH 50
#define TT 96
#define NPRED 12
#define NTH 64
#define EPB 2   // batch elements per block (per thread) — weights shared in registers

typedef unsigned long long u64;

__device__ __forceinline__ u64 pk2(float lo, float hi) {
    u64 r; asm("mov.b64 %0, {%1,%2};" : "=l"(r) : "f"(lo), "f"(hi)); return r;
}
__device__ __forceinline__ void upk2(u64 v, float &lo, float &hi) {
    asm("mov.b64 {%0,%1}, %2;" : "=f"(lo), "=f"(hi) : "l"(v));
}
__device__ __forceinline__ u64 ffma2(u64 a, u64 b, u64 c) {
    u64 d; asm("fma.rn.f32x2 %0, %1, %2, %3;" : "=l"(d) : "l"(a), "l"(b), "l"(c)); return d;
}
__device__ __forceinline__ float ftanh(float x) {
    float y; asm("tanh.approx.f32 %0, %1;" : "=f"(y) : "f"(x)); return y;
}
__device__ __forceinline__ float fsig(float x) {
    return fmaf(0.5f, ftanh(0.5f * x), 0.5f);
}

__global__ __launch_bounds__(NTH)
void lstm_recursive_kernel(const float* __restrict__ x,
                           const float* __restrict__ W_ih,
                           const float* __restrict__ W_hh,
                           const float* __restrict__ b_ih,
                           const float* __restrict__ b_hh,
                           const float* __restrict__ W_fc,
                           const float* __restrict__ b_fc,
                           float* __restrict__ out) {
    const int j  = threadIdx.x;                    // 0..63, ALL lanes active (branchless)
    const int jr = (j < HH) ? j : (HH - 1);        // clamped row: lanes 50-63 duplicate row 49
    const int b0 = blockIdx.x * EPB;

    // h buffers padded to 64: [0..49] real, [50..63] scratch written by clamped lanes
    __shared__ __align__(16) float sh[EPB][2][64];
    __shared__ float swin[EPB][TT + NPRED];
    __shared__ float sred[EPB][64];

#pragma unroll
    for (int e = 0; e < EPB; e++)
        for (int i = j; i < TT; i += NTH) swin[e][i] = x[(b0 + e) * TT + i];

    // thread owns gate rows jr, jr+50, jr+100, jr+150 (i,f,g,o) for BOTH elements
    u64 w[4][25];                    // 200 regs of packed W_hh K-pairs (shared across elements)
    float wih[4], bsum[4];
#pragma unroll
    for (int g = 0; g < 4; g++) {
        const int row = g * HH + jr;
        const float2* wr = (const float2*)(W_hh + row * HH);   // 8B aligned
#pragma unroll
        for (int k = 0; k < 25; k++) {
            float2 v = wr[k];
            w[g][k] = pk2(v.x, v.y);
        }
        wih[g]  = W_ih[row];
        bsum[g] = b_ih[row] + b_hh[row];
    }
    const float wfc = (j < HH) ? W_fc[jr] : 0.0f;   // zero so padded sred entries are 0
    const float bfc = b_fc[0];

    for (int p = 0; p < NPRED; p++) {
#pragma unroll
        for (int e = 0; e < EPB; e++) { sh[e][0][j] = 0.0f; sh[e][1][j] = 0.0f; }
        float c[EPB], hnew[EPB];
#pragma unroll
        for (int e = 0; e < EPB; e++) { c[e] = 0.0f; hnew[e] = 0.0f; }
        __syncthreads();

#pragma unroll 1
        for (int t = 0; t < TT; t++) {
            const int buf = t & 1;
            // 4 accumulator pairs per element -> 8 independent FFMA2 chains
            u64 a0[EPB], a1[EPB], a2[EPB], a3[EPB];
#pragma unroll
            for (int e = 0; e < EPB; e++) {
                const float xt = swin[e][p + t];
                a0[e] = pk2(fmaf(xt, wih[0], bsum[0]), 0.0f);
                a1[e] = pk2(fmaf(xt, wih[1], bsum[1]), 0.0f);
                a2[e] = pk2(fmaf(xt, wih[2], bsum[2]), 0.0f);
                a3[e] = pk2(fmaf(xt, wih[3], bsum[3]), 0.0f);
            }
            const ulonglong2* h0 = (const ulonglong2*)sh[0][buf];
            const ulonglong2* h1 = (const ulonglong2*)sh[1][buf];
#pragma unroll
            for (int cc = 0; cc < 12; cc++) {
                ulonglong2 hvA = h0[cc];           // LDS.128: hA[4cc..4cc+3] (broadcast)
                ulonglong2 hvB = h1[cc];
                a0[0] = ffma2(w[0][2 * cc], hvA.x, a0[0]);
                a1[0] = ffma2(w[1][2 * cc], hvA.x, a1[0]);
                a2[0] = ffma2(w[2][2 * cc], hvA.x, a2[0]);
                a3[0] = ffma2(w[3][2 * cc], hvA.x, a3[0]);
                a0[1] = ffma2(w[0][2 * cc], hvB.x, a0[1]);
                a1[1] = ffma2(w[1][2 * cc], hvB.x, a1[1]);
                a2[1] = ffma2(w[2][2 * cc], hvB.x, a2[1]);
                a3[1] = ffma2(w[3][2 * cc], hvB.x, a3[1]);
                a0[0] = ffma2(w[0][2 * cc + 1], hvA.y, a0[0]);
                a1[0] = ffma2(w[1][2 * cc + 1], hvA.y, a1[0]);
                a2[0] = ffma2(w[2][2 * cc + 1], hvA.y, a2[0]);
                a3[0] = ffma2(w[3][2 * cc + 1], hvA.y, a3[0]);
                a0[1] = ffma2(w[0][2 * cc + 1], hvB.y, a0[1]);
                a1[1] = ffma2(w[1][2 * cc + 1], hvB.y, a1[1]);
                a2[1] = ffma2(w[2][2 * cc + 1], hvB.y, a2[1]);
                a3[1] = ffma2(w[3][2 * cc + 1], hvB.y, a3[1]);
            }
            {   // k = 48, 49
                u64 htA = ((const u64*)sh[0][buf])[24];
                u64 htB = ((const u64*)sh[1][buf])[24];
                a0[0] = ffma2(w[0][24], htA, a0[0]);
                a1[0] = ffma2(w[1][24], htA, a1[0]);
                a2[0] = ffma2(w[2][24], htA, a2[0]);
                a3[0] = ffma2(w[3][24], htA, a3[0]);
                a0[1] = ffma2(w[0][24], htB, a0[1]);
                a1[1] = ffma2(w[1][24], htB, a1[1]);
                a2[1] = ffma2(w[2][24], htB, a2[1]);
                a3[1] = ffma2(w[3][24], htB, a3[1]);
            }
#pragma unroll
            for (int e = 0; e < EPB; e++) {
                float l0, hi0, l1, hi1, l2, hi2, l3, hi3;
                upk2(a0[e], l0, hi0);
                upk2(a1[e], l1, hi1);
                upk2(a2[e], l2, hi2);
                upk2(a3[e], l3, hi3);
                const float i_ = fsig(l0 + hi0);
                const float f_ = fsig(l1 + hi1);
                const float g_ = ftanh(l2 + hi2);
                const float o_ = fsig(l3 + hi3);
                c[e]    = fmaf(f_, c[e], i_ * g_);
                hnew[e] = o_ * ftanh(c[e]);
                sh[e][buf ^ 1][j] = hnew[e];       // lanes 50-63 write pad slots (harmless)
            }
            __syncthreads();                       // new h visible for next step
        }

        // FC head: out = h . W_fc + b_fc  (wfc==0 for pad lanes -> sred pad entries are 0)
#pragma unroll
        for (int e = 0; e < EPB; e++) sred[e][j] = hnew[e] * wfc;
        __syncthreads();
        if (j < EPB) {
            float s = bfc;
#pragma unroll
            for (int k = 0; k < HH; k++) s += sred[j][k];
            swin[j][TT + p] = s;
            out[(b0 + j) * NPRED + p] = s;
        }
        __syncthreads();
    }
}

extern "C" void kernel_launch(void* const* d_in, const int* in_sizes, int n_in,
                              void* d_out, int out_size) {
    const float* x    = (const float*)d_in[0];
    const float* W_ih = (const float*)d_in[1];
    const float* W_hh = (const float*)d_in[2];
    const float* b_ih = (const float*)d_in[3];
    const float* b_hh = (const float*)d_in[4];
    const float* W_fc = (const float*)d_in[5];
    const float* b_fc = (const float*)d_in[6];
    float* out = (float*)d_out;

    const int B = out_size / NPRED;               // 1024
    lstm_recursive_kernel<<<B / EPB, NTH>>>(x, W_ih, W_hh, b_ih, b_hh, W_fc, b_fc, out);
}